// round 8
// baseline (speedup 1.0000x reference)
#include <cuda_runtime.h>
#include <math.h>

// GMM log-prob: out[n,k] = cst_k - 0.5 * sum_e (x_n . L_k[:,e] - mp[k,e])^2
// N=16384, K=200, D=64.

#define KCOMP 200
#define DF    64
#define TN    128      // n-rows per CTA
#define NTHREADS 256

typedef unsigned long long ull;

__device__ float g_mp[KCOMP * DF];   // means @ prec_chol, per k
__device__ float g_cst[KCOMP];       // logdet_k - 0.5*D*log(2pi)

// ---- packed f32x2 helpers (sm_103a) ----
__device__ __forceinline__ ull pack2_bcast(float a) {
    ull r;
    asm("mov.b64 %0, {%1, %1};" : "=l"(r) : "f"(a));
    return r;
}
__device__ __forceinline__ float2 unpack2(ull v) {
    float2 r;
    asm("mov.b64 {%0, %1}, %2;" : "=f"(r.x), "=f"(r.y) : "l"(v));
    return r;
}
__device__ __forceinline__ void fma2(ull& d, ull a, ull b) {
    asm("fma.rn.f32x2 %0, %1, %2, %0;" : "+l"(d) : "l"(a), "l"(b));
}

// ---------------------------------------------------------------------------
// Kernel 1: per-component constants. grid = K, block = 64 (one thread per e).
// ---------------------------------------------------------------------------
__global__ void gmm_precompute_kernel(const float* __restrict__ means,
                                      const float* __restrict__ pc) {
    const int k = blockIdx.x;
    const int e = threadIdx.x;
    const float* L = pc + (size_t)k * DF * DF;
    const float* mu = means + k * DF;

    float acc = 0.0f;
#pragma unroll 8
    for (int d = 0; d < DF; ++d)
        acc = fmaf(mu[d], L[d * DF + e], acc);
    g_mp[k * DF + e] = acc;

    // log-det: sum of log(diag)
    float lg = logf(L[e * DF + e]);
#pragma unroll
    for (int off = 16; off; off >>= 1)
        lg += __shfl_xor_sync(0xffffffffu, lg, off);
    __shared__ float s[2];
    if ((e & 31) == 0) s[e >> 5] = lg;
    __syncthreads();
    if (e == 0)
        g_cst[k] = (s[0] + s[1]) - 0.5f * DF * 1.8378770664093453f; // log(2*pi)
}

// ---------------------------------------------------------------------------
// Kernel 2: main compute. grid = (N/TN, K), block = 256.
// Warp layout: warp w -> et = w & 3 (e-slice of 16), nb = w >> 2 (row half).
// Thread owns rows r0 = nb*64 + 2*lane, r1 = r0+1, cols e0 = et*16 .. +15.
// smem: Ls[64*64] (16KB) + xs[64*128] transposed+swizzled (32KB) = 48KB.
// ---------------------------------------------------------------------------
__global__ void __launch_bounds__(NTHREADS, 2)
gmm_main_kernel(const float* __restrict__ x,
                const float* __restrict__ pc,
                float* __restrict__ out) {
    __shared__ float Ls[DF * DF];       // [d][e], row-contiguous
    __shared__ float xs[DF * TN];       // [d][n ^ (2*(d&15))]  transposed, swizzled

    const int tid = threadIdx.x;
    const int k  = blockIdx.y;
    const int n0 = blockIdx.x * TN;

    // --- load L tile (coalesced, conflict-free) ---
    {
        const float4* Lg4 = (const float4*)(pc + (size_t)k * DF * DF);
        float4* Ls4 = (float4*)Ls;
#pragma unroll
        for (int i = tid; i < DF * DF / 4; i += NTHREADS)
            Ls4[i] = Lg4[i];
    }
    // --- load x tile, transpose into smem with XOR swizzle ---
    {
        const float2* xg2 = (const float2*)(x + (size_t)n0 * DF);
#pragma unroll
        for (int i = tid; i < TN * (DF / 2); i += NTHREADS) {
            int n = i >> 5;          // row 0..127
            int j = i & 31;          // float2 index within row
            int d = 2 * j;
            float2 v = xg2[n * 32 + j];
            xs[(d    ) * TN + (n ^ (2 * ( d      & 15)))] = v.x;
            xs[(d + 1) * TN + (n ^ (2 * ((d + 1) & 15)))] = v.y;
        }
    }
    __syncthreads();

    const int warp = tid >> 5, lane = tid & 31;
    const int et = warp & 3, nb = warp >> 2;
    const int e0 = et * 16;
    const int r0 = nb * 64 + 2 * lane;   // even

    ull acc0[8], acc1[8];
#pragma unroll
    for (int j = 0; j < 8; ++j) { acc0[j] = 0ull; acc1[j] = 0ull; }

#pragma unroll 16
    for (int d = 0; d < DF; ++d) {
        const int sw = 2 * (d & 15);
        // one LDS.64 fetches x[r0][d] and x[r1][d]
        float2 xv = *(const float2*)(xs + d * TN + (r0 ^ sw));
        ull xa = pack2_bcast(xv.x);
        ull xb = pack2_bcast(xv.y);
        // L[d][e0..e0+15]: full warp broadcast, 4x LDS.128
        const ulonglong2* lp = (const ulonglong2*)(Ls + d * DF + e0);
        ulonglong2 l0 = lp[0], l1 = lp[1], l2 = lp[2], l3 = lp[3];
        ull lv[8] = { l0.x, l0.y, l1.x, l1.y, l2.x, l2.y, l3.x, l3.y };
#pragma unroll
        for (int j = 0; j < 8; ++j) {
            fma2(acc0[j], xa, lv[j]);
            fma2(acc1[j], xb, lv[j]);
        }
    }

    // --- epilogue: q = sum_e (y - mp)^2 for each of the 2 rows ---
    const float2* mp2 = (const float2*)(g_mp + k * DF + e0);
    float q0 = 0.0f, q1 = 0.0f;
#pragma unroll
    for (int j = 0; j < 8; ++j) {
        float2 m  = mp2[j];
        float2 y0 = unpack2(acc0[j]);
        float2 y1 = unpack2(acc1[j]);
        float t;
        t = y0.x - m.x; q0 = fmaf(t, t, q0);
        t = y0.y - m.y; q0 = fmaf(t, t, q0);
        t = y1.x - m.x; q1 = fmaf(t, t, q1);
        t = y1.y - m.y; q1 = fmaf(t, t, q1);
    }

    // combine the 4 e-slice warps (reuse xs as scratch after the mainloop)
    __syncthreads();
    float2* red = (float2*)xs;   // [4][64] float2
    red[et * 64 + nb * 32 + lane] = make_float2(q0, q1);
    __syncthreads();

    if (tid < 64) {
        float2 s0 = red[tid], s1 = red[64 + tid], s2 = red[128 + tid], s3 = red[192 + tid];
        float qa = (s0.x + s1.x) + (s2.x + s3.x);
        float qb = (s0.y + s1.y) + (s2.y + s3.y);
        int nbb = tid >> 5, ln = tid & 31;
        int rr0 = nbb * 64 + 2 * ln;
        float cst = g_cst[k];
        out[(n0 + rr0    ) * KCOMP + k] = cst - 0.5f * qa;
        out[(n0 + rr0 + 1) * KCOMP + k] = cst - 0.5f * qb;
    }
}

// ---------------------------------------------------------------------------
extern "C" void kernel_launch(void* const* d_in, const int* in_sizes, int n_in,
                              void* d_out, int out_size) {
    const float* x     = (const float*)d_in[0];  // [16384, 64]
    const float* means = (const float*)d_in[1];  // [200, 64]
    const float* pc    = (const float*)d_in[2];  // [200, 64, 64]
    float* out = (float*)d_out;                  // [16384, 200]

    gmm_precompute_kernel<<<KCOMP, 64>>>(means, pc);

    dim3 grid(16384 / TN, KCOMP);  // (128, 200)
    gmm_main_kernel<<<grid, NTHREADS>>>(x, pc, out);
}

// round 9
// speedup vs baseline: 1.0004x; 1.0004x over previous
#include <cuda_runtime.h>
#include <math.h>

// GMM log-prob: out[n,k] = cst_k - 0.5 * sum_e (x_n . L_k[:,e] - mp[k,e])^2
// N=16384, K=200, D=64.

#define KCOMP 200
#define DF    64
#define TN    128      // n-rows per CTA
#define NTHREADS 256

typedef unsigned long long ull;

__device__ float g_mp[KCOMP * DF];   // means @ prec_chol, per k
__device__ float g_cst[KCOMP];       // logdet_k - 0.5*D*log(2pi)

// ---- packed f32x2 helpers (sm_103a) ----
__device__ __forceinline__ ull pack2_bcast(float a) {
    ull r;
    asm("mov.b64 %0, {%1, %1};" : "=l"(r) : "f"(a));
    return r;
}
__device__ __forceinline__ float2 unpack2(ull v) {
    float2 r;
    asm("mov.b64 {%0, %1}, %2;" : "=f"(r.x), "=f"(r.y) : "l"(v));
    return r;
}
__device__ __forceinline__ void fma2(ull& d, ull a, ull b) {
    asm("fma.rn.f32x2 %0, %1, %2, %0;" : "+l"(d) : "l"(a), "l"(b));
}

// ---------------------------------------------------------------------------
// Kernel 1: per-component constants. grid = K, block = 64 (one thread per e).
// ---------------------------------------------------------------------------
__global__ void gmm_precompute_kernel(const float* __restrict__ means,
                                      const float* __restrict__ pc) {
    const int k = blockIdx.x;
    const int e = threadIdx.x;
    const float* L = pc + (size_t)k * DF * DF;
    const float* mu = means + k * DF;

    float acc = 0.0f;
#pragma unroll 8
    for (int d = 0; d < DF; ++d)
        acc = fmaf(mu[d], L[d * DF + e], acc);
    g_mp[k * DF + e] = acc;

    // log-det: sum of log(diag)
    float lg = logf(L[e * DF + e]);
#pragma unroll
    for (int off = 16; off; off >>= 1)
        lg += __shfl_xor_sync(0xffffffffu, lg, off);
    __shared__ float s[2];
    if ((e & 31) == 0) s[e >> 5] = lg;
    __syncthreads();
    if (e == 0)
        g_cst[k] = (s[0] + s[1]) - 0.5f * DF * 1.8378770664093453f; // log(2*pi)
}

// ---------------------------------------------------------------------------
// Kernel 2: main compute. grid = (N/TN, K), block = 256.
// Warp layout: warp w -> et = w & 3 (e-slice of 16), nb = w >> 2 (row half).
// Thread owns rows r0 = nb*64 + 2*lane, r1 = r0+1, cols e0 = et*16 .. +15.
// smem: Ls[64*64] (16KB) + xs[64*128] transposed+swizzled (32KB) = 48KB.
// ---------------------------------------------------------------------------
__global__ void __launch_bounds__(NTHREADS, 2)
gmm_main_kernel(const float* __restrict__ x,
                const float* __restrict__ pc,
                float* __restrict__ out) {
    __shared__ float Ls[DF * DF];       // [d][e], row-contiguous
    __shared__ float xs[DF * TN];       // [d][n ^ (2*(d&15))]  transposed, swizzled

    const int tid = threadIdx.x;
    const int k  = blockIdx.y;
    const int n0 = blockIdx.x * TN;

    // --- load L tile (coalesced, conflict-free) ---
    {
        const float4* Lg4 = (const float4*)(pc + (size_t)k * DF * DF);
        float4* Ls4 = (float4*)Ls;
#pragma unroll
        for (int i = tid; i < DF * DF / 4; i += NTHREADS)
            Ls4[i] = Lg4[i];
    }
    // --- load x tile, transpose into smem with XOR swizzle ---
    {
        const float2* xg2 = (const float2*)(x + (size_t)n0 * DF);
#pragma unroll
        for (int i = tid; i < TN * (DF / 2); i += NTHREADS) {
            int n = i >> 5;          // row 0..127
            int j = i & 31;          // float2 index within row
            int d = 2 * j;
            float2 v = xg2[n * 32 + j];
            xs[(d    ) * TN + (n ^ (2 * ( d      & 15)))] = v.x;
            xs[(d + 1) * TN + (n ^ (2 * ((d + 1) & 15)))] = v.y;
        }
    }
    __syncthreads();

    const int warp = tid >> 5, lane = tid & 31;
    const int et = warp & 3, nb = warp >> 2;
    const int e0 = et * 16;
    const int r0 = nb * 64 + 2 * lane;   // even

    ull acc0[8], acc1[8];
#pragma unroll
    for (int j = 0; j < 8; ++j) { acc0[j] = 0ull; acc1[j] = 0ull; }

#pragma unroll 16
    for (int d = 0; d < DF; ++d) {
        const int sw = 2 * (d & 15);
        // one LDS.64 fetches x[r0][d] and x[r1][d]
        float2 xv = *(const float2*)(xs + d * TN + (r0 ^ sw));
        ull xa = pack2_bcast(xv.x);
        ull xb = pack2_bcast(xv.y);
        // L[d][e0..e0+15]: full warp broadcast, 4x LDS.128
        const ulonglong2* lp = (const ulonglong2*)(Ls + d * DF + e0);
        ulonglong2 l0 = lp[0], l1 = lp[1], l2 = lp[2], l3 = lp[3];
        ull lv[8] = { l0.x, l0.y, l1.x, l1.y, l2.x, l2.y, l3.x, l3.y };
#pragma unroll
        for (int j = 0; j < 8; ++j) {
            fma2(acc0[j], xa, lv[j]);
            fma2(acc1[j], xb, lv[j]);
        }
    }

    // --- epilogue: q = sum_e (y - mp)^2 for each of the 2 rows ---
    const float2* mp2 = (const float2*)(g_mp + k * DF + e0);
    float q0 = 0.0f, q1 = 0.0f;
#pragma unroll
    for (int j = 0; j < 8; ++j) {
        float2 m  = mp2[j];
        float2 y0 = unpack2(acc0[j]);
        float2 y1 = unpack2(acc1[j]);
        float t;
        t = y0.x - m.x; q0 = fmaf(t, t, q0);
        t = y0.y - m.y; q0 = fmaf(t, t, q0);
        t = y1.x - m.x; q1 = fmaf(t, t, q1);
        t = y1.y - m.y; q1 = fmaf(t, t, q1);
    }

    // combine the 4 e-slice warps (reuse xs as scratch after the mainloop)
    __syncthreads();
    float2* red = (float2*)xs;   // [4][64] float2
    red[et * 64 + nb * 32 + lane] = make_float2(q0, q1);
    __syncthreads();

    if (tid < 64) {
        float2 s0 = red[tid], s1 = red[64 + tid], s2 = red[128 + tid], s3 = red[192 + tid];
        float qa = (s0.x + s1.x) + (s2.x + s3.x);
        float qb = (s0.y + s1.y) + (s2.y + s3.y);
        int nbb = tid >> 5, ln = tid & 31;
        int rr0 = nbb * 64 + 2 * ln;
        float cst = g_cst[k];
        out[(n0 + rr0    ) * KCOMP + k] = cst - 0.5f * qa;
        out[(n0 + rr0 + 1) * KCOMP + k] = cst - 0.5f * qb;
    }
}

// ---------------------------------------------------------------------------
extern "C" void kernel_launch(void* const* d_in, const int* in_sizes, int n_in,
                              void* d_out, int out_size) {
    const float* x     = (const float*)d_in[0];  // [16384, 64]
    const float* means = (const float*)d_in[1];  // [200, 64]
    const float* pc    = (const float*)d_in[2];  // [200, 64, 64]
    float* out = (float*)d_out;                  // [16384, 200]

    gmm_precompute_kernel<<<KCOMP, 64>>>(means, pc);

    dim3 grid(16384 / TN, KCOMP);  // (128, 200)
    gmm_main_kernel<<<grid, NTHREADS>>>(x, pc, out);
}

// round 10
// speedup vs baseline: 1.0015x; 1.0011x over previous
#include <cuda_runtime.h>
#include <math.h>

// GMM log-prob: out[n,k] = cst_k - 0.5 * sum_e (x_n . L_k[:,e] - mp[k,e])^2
// N=16384, K=200, D=64.

#define KCOMP 200
#define DF    64
#define TN    128      // n-rows per CTA
#define NTHREADS 256

typedef unsigned long long ull;

__device__ float g_mp[KCOMP * DF];   // means @ prec_chol, per k
__device__ float g_cst[KCOMP];       // logdet_k - 0.5*D*log(2pi)

// ---- packed f32x2 helpers (sm_103a) ----
__device__ __forceinline__ ull pack2_bcast(float a) {
    ull r;
    asm("mov.b64 %0, {%1, %1};" : "=l"(r) : "f"(a));
    return r;
}
__device__ __forceinline__ float2 unpack2(ull v) {
    float2 r;
    asm("mov.b64 {%0, %1}, %2;" : "=f"(r.x), "=f"(r.y) : "l"(v));
    return r;
}
__device__ __forceinline__ void fma2(ull& d, ull a, ull b) {
    asm("fma.rn.f32x2 %0, %1, %2, %0;" : "+l"(d) : "l"(a), "l"(b));
}

// ---------------------------------------------------------------------------
// Kernel 1: per-component constants. grid = K, block = 64 (one thread per e).
// ---------------------------------------------------------------------------
__global__ void gmm_precompute_kernel(const float* __restrict__ means,
                                      const float* __restrict__ pc) {
    const int k = blockIdx.x;
    const int e = threadIdx.x;
    const float* L = pc + (size_t)k * DF * DF;
    const float* mu = means + k * DF;

    float acc = 0.0f;
#pragma unroll 8
    for (int d = 0; d < DF; ++d)
        acc = fmaf(mu[d], L[d * DF + e], acc);
    g_mp[k * DF + e] = acc;

    // log-det: sum of log(diag)
    float lg = logf(L[e * DF + e]);
#pragma unroll
    for (int off = 16; off; off >>= 1)
        lg += __shfl_xor_sync(0xffffffffu, lg, off);
    __shared__ float s[2];
    if ((e & 31) == 0) s[e >> 5] = lg;
    __syncthreads();
    if (e == 0)
        g_cst[k] = (s[0] + s[1]) - 0.5f * DF * 1.8378770664093453f; // log(2*pi)
}

// ---------------------------------------------------------------------------
// Kernel 2: main compute. grid = (N/TN, K), block = 256.
// Warp layout: warp w -> et = w & 3 (e-slice of 16), nb = w >> 2 (row half).
// Thread owns rows r0 = nb*64 + 2*lane, r1 = r0+1, cols e0 = et*16 .. +15.
// smem: Ls[64*64] (16KB) + xs[64*128] transposed+swizzled (32KB) = 48KB.
// ---------------------------------------------------------------------------
__global__ void __launch_bounds__(NTHREADS, 2)
gmm_main_kernel(const float* __restrict__ x,
                const float* __restrict__ pc,
                float* __restrict__ out) {
    __shared__ float Ls[DF * DF];       // [d][e], row-contiguous
    __shared__ float xs[DF * TN];       // [d][n ^ (2*(d&15))]  transposed, swizzled

    const int tid = threadIdx.x;
    const int k  = blockIdx.y;
    const int n0 = blockIdx.x * TN;

    // --- load L tile (coalesced, conflict-free) ---
    {
        const float4* Lg4 = (const float4*)(pc + (size_t)k * DF * DF);
        float4* Ls4 = (float4*)Ls;
#pragma unroll
        for (int i = tid; i < DF * DF / 4; i += NTHREADS)
            Ls4[i] = Lg4[i];
    }
    // --- load x tile, transpose into smem with XOR swizzle ---
    {
        const float2* xg2 = (const float2*)(x + (size_t)n0 * DF);
#pragma unroll
        for (int i = tid; i < TN * (DF / 2); i += NTHREADS) {
            int n = i >> 5;          // row 0..127
            int j = i & 31;          // float2 index within row
            int d = 2 * j;
            float2 v = xg2[n * 32 + j];
            xs[(d    ) * TN + (n ^ (2 * ( d      & 15)))] = v.x;
            xs[(d + 1) * TN + (n ^ (2 * ((d + 1) & 15)))] = v.y;
        }
    }
    __syncthreads();

    const int warp = tid >> 5, lane = tid & 31;
    const int et = warp & 3, nb = warp >> 2;
    const int e0 = et * 16;
    const int r0 = nb * 64 + 2 * lane;   // even

    ull acc0[8], acc1[8];
#pragma unroll
    for (int j = 0; j < 8; ++j) { acc0[j] = 0ull; acc1[j] = 0ull; }

#pragma unroll 16
    for (int d = 0; d < DF; ++d) {
        const int sw = 2 * (d & 15);
        // one LDS.64 fetches x[r0][d] and x[r1][d]
        float2 xv = *(const float2*)(xs + d * TN + (r0 ^ sw));
        ull xa = pack2_bcast(xv.x);
        ull xb = pack2_bcast(xv.y);
        // L[d][e0..e0+15]: full warp broadcast, 4x LDS.128
        const ulonglong2* lp = (const ulonglong2*)(Ls + d * DF + e0);
        ulonglong2 l0 = lp[0], l1 = lp[1], l2 = lp[2], l3 = lp[3];
        ull lv[8] = { l0.x, l0.y, l1.x, l1.y, l2.x, l2.y, l3.x, l3.y };
#pragma unroll
        for (int j = 0; j < 8; ++j) {
            fma2(acc0[j], xa, lv[j]);
            fma2(acc1[j], xb, lv[j]);
        }
    }

    // --- epilogue: q = sum_e (y - mp)^2 for each of the 2 rows ---
    const float2* mp2 = (const float2*)(g_mp + k * DF + e0);
    float q0 = 0.0f, q1 = 0.0f;
#pragma unroll
    for (int j = 0; j < 8; ++j) {
        float2 m  = mp2[j];
        float2 y0 = unpack2(acc0[j]);
        float2 y1 = unpack2(acc1[j]);
        float t;
        t = y0.x - m.x; q0 = fmaf(t, t, q0);
        t = y0.y - m.y; q0 = fmaf(t, t, q0);
        t = y1.x - m.x; q1 = fmaf(t, t, q1);
        t = y1.y - m.y; q1 = fmaf(t, t, q1);
    }

    // combine the 4 e-slice warps (reuse xs as scratch after the mainloop)
    __syncthreads();
    float2* red = (float2*)xs;   // [4][64] float2
    red[et * 64 + nb * 32 + lane] = make_float2(q0, q1);
    __syncthreads();

    if (tid < 64) {
        float2 s0 = red[tid], s1 = red[64 + tid], s2 = red[128 + tid], s3 = red[192 + tid];
        float qa = (s0.x + s1.x) + (s2.x + s3.x);
        float qb = (s0.y + s1.y) + (s2.y + s3.y);
        int nbb = tid >> 5, ln = tid & 31;
        int rr0 = nbb * 64 + 2 * ln;
        float cst = g_cst[k];
        out[(n0 + rr0    ) * KCOMP + k] = cst - 0.5f * qa;
        out[(n0 + rr0 + 1) * KCOMP + k] = cst - 0.5f * qb;
    }
}

// ---------------------------------------------------------------------------
extern "C" void kernel_launch(void* const* d_in, const int* in_sizes, int n_in,
                              void* d_out, int out_size) {
    const float* x     = (const float*)d_in[0];  // [16384, 64]
    const float* means = (const float*)d_in[1];  // [200, 64]
    const float* pc    = (const float*)d_in[2];  // [200, 64, 64]
    float* out = (float*)d_out;                  // [16384, 200]

    gmm_precompute_kernel<<<KCOMP, 64>>>(means, pc);

    dim3 grid(16384 / TN, KCOMP);  // (128, 200)
    gmm_main_kernel<<<grid, NTHREADS>>>(x, pc, out);
}